// round 17
// baseline (speedup 1.0000x reference)
#include <cuda_runtime.h>
#include <cuda_fp16.h>
#include <math.h>
#include <stdint.h>

// ---------------- problem constants ----------------
#define B_    4
#define S_    2048
#define D_    2048
#define H_    16
#define DH_   128
#define DFF_  8192
#define MTOK  (B_*S_)          // 8192
#define D3_   (3*D_)           // 6144
#define GSPL  4                // gram split-K over tokens

// ---------------- scratch (device globals) ----------------
__device__ float   g_WsmP [GSPL][64][DH_*DH_];        // gram split-K partials (fp32)
__device__ float   g_R2   [(size_t)MTOK * D_];        // R2 fp32 (final LN input)
__device__ __half  g_R1h  [(size_t)MTOK * D_];        // R1 fp16
__device__ __half  g_QKV16[(size_t)MTOK * D3_];       // QKV fp16 [token][6144]
__device__ __half  g_w16  [64 * DH_ * DH_];           // softmax probs fp16
__device__ __half  g_x16  [(size_t)MTOK * D_];
__device__ __half  g_W116 [(size_t)D3_  * D_];
__device__ __half  g_W216 [(size_t)D_   * D_];
__device__ __half  g_fc16 [(size_t)DFF_ * D_];
__device__ __half  g_pj16 [(size_t)D_   * DFF_];
__device__ __half  g_A16  [(size_t)MTOK * D_];
__device__ __half  g_L116 [(size_t)MTOK * D_];        // LN1 fp16 (fc operand + R2 residual)
__device__ __half  g_H16  [(size_t)MTOK * DFF_];
__device__ double  g_part [2048];
__device__ float   g_stats[2];

__device__ __forceinline__ float gelu_f(float x) {
    float u = 0.7978845608028654f * (x + 0.044715f * x * x * x);
    float t;
    asm("tanh.approx.f32 %0, %1;" : "=f"(t) : "f"(u));
    return 0.5f * x * (1.0f + t);
}

// ================= baseline-PTX helpers =================
__device__ __forceinline__ uint32_t smem_u32(const void* p) {
    uint32_t a;
    asm("{ .reg .u64 t; cvta.to.shared.u64 t, %1; cvt.u32.u64 %0, t; }" : "=r"(a) : "l"(p));
    return a;
}
__device__ __forceinline__ void cp16(uint32_t s, const void* g) {
    asm volatile("cp.async.cg.shared.global [%0], [%1], 16;" :: "r"(s), "l"(g));
}
#define CP_COMMIT() asm volatile("cp.async.commit_group;" ::: "memory")
template<int N> __device__ __forceinline__ void cp_wait() {
    asm volatile("cp.async.wait_group %0;" :: "n"(N) : "memory");
}
__device__ __forceinline__ uint32_t swz128(uint32_t off) { return off ^ ((off >> 3) & 0x70); }

#define LDSM4(r, addr) \
    asm volatile("ldmatrix.sync.aligned.m8n8.x4.shared.b16 {%0,%1,%2,%3}, [%4];" \
        : "=r"((r)[0]), "=r"((r)[1]), "=r"((r)[2]), "=r"((r)[3]) : "r"(addr))

#define LDSM4T(r, addr) \
    asm volatile("ldmatrix.sync.aligned.m8n8.x4.trans.shared.b16 {%0,%1,%2,%3}, [%4];" \
        : "=r"((r)[0]), "=r"((r)[1]), "=r"((r)[2]), "=r"((r)[3]) : "r"(addr))

#define MMA16816(c, a, b0, b1) \
    asm volatile("mma.sync.aligned.m16n8k16.row.col.f32.f16.f16.f32 " \
        "{%0,%1,%2,%3},{%4,%5,%6,%7},{%8,%9},{%0,%1,%2,%3};" \
        : "+f"((c)[0]), "+f"((c)[1]), "+f"((c)[2]), "+f"((c)[3]) \
        : "r"((a)[0]), "r"((a)[1]), "r"((a)[2]), "r"((a)[3]), "r"(b0), "r"(b1))

// ================= mma.sync GEMM (proven config, single-sync mainloop) ======
#define NS          3
#define STAGE_BYTES 32768
#define TCG_SMEM    (NS * STAGE_BYTES)

__device__ __forceinline__ void load_tile(
    const __half* __restrict__ A, const __half* __restrict__ Bw,
    uint32_t tA, uint32_t tB, long long rowA0, long long rowB0,
    long long ldg, long long k0, int tid)
{
    #pragma unroll
    for (int i = 0; i < 4; i++) {
        int q = tid + 256 * i; int r = q >> 3, c = q & 7;
        cp16(tA + swz128(r * 128 + c * 16), A + (rowA0 + r) * ldg + k0 + c * 8);
    }
    #pragma unroll
    for (int i = 0; i < 4; i++) {
        int q = tid + 256 * i; int r = q >> 3, c = q & 7;
        cp16(tB + swz128(r * 128 + c * 16), Bw + (rowB0 + r) * ldg + k0 + c * 8);
    }
}

// RES: fp32 residual. RES16: fp16 residual. H16: fp16 output copy. STATS: LN partials.
template<bool GELU, bool RES, bool RES16, bool H16, bool STATS>
__global__ __launch_bounds__(256, 2) void mma_gemm(
    const __half* __restrict__ A, const __half* __restrict__ Bw,
    int K, const float* __restrict__ bias, const float* __restrict__ residf,
    const __half* __restrict__ resid16,
    float* __restrict__ Cf, __half* __restrict__ C16, int N)
{
    extern __shared__ char smem[];
    const uint32_t tiles = smem_u32(smem);
    const int tid  = threadIdx.x;
    const int wid  = tid >> 5, lane = tid & 31;
    const int wm   = wid >> 1, wn = wid & 1;

    const long long ldg   = K;
    const long long rowA0 = (long long)blockIdx.y * 128;
    const long long rowB0 = (long long)blockIdx.x * 128;
    const int total = K >> 6;

    float acc[2][8][4];
    #pragma unroll
    for (int i = 0; i < 2; i++)
        #pragma unroll
        for (int j = 0; j < 8; j++)
            #pragma unroll
            for (int q = 0; q < 4; q++) acc[i][j][q] = 0.0f;

    for (int s = 0; s < 2; s++) {
        load_tile(A, Bw, tiles + s * STAGE_BYTES, tiles + s * STAGE_BYTES + 16384,
                  rowA0, rowB0, ldg, (long long)s << 6, tid);
        CP_COMMIT();
    }

    for (int m = 0; m < total; m++) {
        cp_wait<1>();
        __syncthreads();
        const int s = m + 2;
        if (s < total) {
            const int slot = s % NS;
            load_tile(A, Bw, tiles + slot * STAGE_BYTES, tiles + slot * STAGE_BYTES + 16384,
                      rowA0, rowB0, ldg, (long long)s << 6, tid);
        }
        CP_COMMIT();

        const uint32_t Asm = tiles + (m % NS) * STAGE_BYTES;
        const uint32_t Bsm = Asm + 16384;
        #pragma unroll
        for (int kk = 0; kk < 4; kk++) {
            uint32_t af[2][4];
            #pragma unroll
            for (int mi = 0; mi < 2; mi++) {
                uint32_t addr = Asm + swz128((wm * 32 + mi * 16 + (lane & 15)) * 128
                                             + kk * 32 + (lane >> 4) * 16);
                LDSM4(af[mi], addr);
            }
            uint32_t bfr[4][4];
            #pragma unroll
            for (int nj = 0; nj < 4; nj++) {
                uint32_t addr = Bsm + swz128((wn * 64 + nj * 16 + (lane & 15)) * 128
                                             + kk * 32 + (lane >> 4) * 16);
                LDSM4(bfr[nj], addr);
            }
            #pragma unroll
            for (int mi = 0; mi < 2; mi++)
                #pragma unroll
                for (int nj = 0; nj < 4; nj++) {
                    MMA16816(acc[mi][2*nj],   af[mi], bfr[nj][0], bfr[nj][2]);
                    MMA16816(acc[mi][2*nj+1], af[mi], bfr[nj][1], bfr[nj][3]);
                }
        }
    }

    float st_s = 0.0f, st_q = 0.0f;
    const long long rowT = rowA0 + wm * 32;
    const long long colT = rowB0 + wn * 64;
    #pragma unroll
    for (int mi = 0; mi < 2; mi++) {
        #pragma unroll
        for (int n8 = 0; n8 < 8; n8++) {
            const long long col = colT + n8 * 8 + (lane & 3) * 2;
            const float b0 = bias[col], b1 = bias[col + 1];
            #pragma unroll
            for (int h = 0; h < 2; h++) {
                const long long row = rowT + mi * 16 + (lane >> 2) + h * 8;
                float v0 = acc[mi][n8][2*h]     + b0;
                float v1 = acc[mi][n8][2*h + 1] + b1;
                if (RES) {
                    const float2 rv = *(const float2*)(residf + row * N + col);
                    v0 += rv.x; v1 += rv.y;
                }
                if (RES16) {
                    const __half2 rh = *(const __half2*)(resid16 + row * N + col);
                    v0 += __half2float(__low2half(rh));
                    v1 += __half2float(__high2half(rh));
                }
                if (GELU) { v0 = gelu_f(v0); v1 = gelu_f(v1); }
                if (STATS) { st_s += v0 + v1; st_q += v0 * v0 + v1 * v1; }
                if (H16) {
                    *(__half2*)(C16 + row * N + col) =
                        __halves2half2(__float2half(v0), __float2half(v1));
                }
                if (Cf != nullptr) {
                    *(float2*)(Cf + row * N + col) = make_float2(v0, v1);
                }
            }
        }
    }
    if (STATS) {
        __syncthreads();
        double* shs = (double*)smem;
        double* shq = shs + 256;
        shs[tid] = (double)st_s; shq[tid] = (double)st_q;
        __syncthreads();
        for (int off = 128; off; off >>= 1) {
            if (tid < off) { shs[tid] += shs[tid + off]; shq[tid] += shq[tid + off]; }
            __syncthreads();
        }
        if (tid == 0) {
            int cta = blockIdx.y * gridDim.x + blockIdx.x;
            g_part[2 * cta] = shs[0];
            g_part[2 * cta + 1] = shq[0];
        }
    }
}

// ================= gram via trans-ldmatrix mma (single-sync) =============
__global__ __launch_bounds__(256, 2) void gram_mma(const __half* __restrict__ QKV)
{
    extern __shared__ char smem[];
    const uint32_t tiles = smem_u32(smem);
    const int tid = threadIdx.x;
    const int wid = tid >> 5, lane = tid & 31;
    const int wm  = wid >> 1, wn = wid & 1;

    const int z = blockIdx.x, split = blockIdx.y;
    const int b = z >> 4, h = z & 15;
    const long long tok0 = (long long)b * S_ + split * (S_ / GSPL);
    const __half* Qb = QKV + tok0 * D3_ + h * DH_;
    const __half* Kb = Qb + D_;
    const int total = (S_ / GSPL) >> 6;

    float acc[2][8][4];
    #pragma unroll
    for (int i = 0; i < 2; i++)
        #pragma unroll
        for (int j = 0; j < 8; j++)
            #pragma unroll
            for (int q = 0; q < 4; q++) acc[i][j][q] = 0.0f;

    auto load_g = [&](uint32_t tA, uint32_t tB, int s0) {
        #pragma unroll
        for (int i = 0; i < 4; i++) {
            int q = tid + 256 * i; int r = q >> 4, c = q & 15;
            cp16(tA + r * 256 + ((c ^ (r & 7)) * 16), Qb + (long long)(s0 + r) * D3_ + c * 8);
        }
        #pragma unroll
        for (int i = 0; i < 4; i++) {
            int q = tid + 256 * i; int r = q >> 4, c = q & 15;
            cp16(tB + r * 256 + ((c ^ (r & 7)) * 16), Kb + (long long)(s0 + r) * D3_ + c * 8);
        }
    };

    for (int s = 0; s < 2; s++) {
        load_g(tiles + s * STAGE_BYTES, tiles + s * STAGE_BYTES + 16384, s << 6);
        CP_COMMIT();
    }

    for (int m = 0; m < total; m++) {
        cp_wait<1>();
        __syncthreads();
        const int s = m + 2;
        if (s < total) {
            const int slot = s % NS;
            load_g(tiles + slot * STAGE_BYTES, tiles + slot * STAGE_BYTES + 16384, s << 6);
        }
        CP_COMMIT();

        const uint32_t Asm = tiles + (m % NS) * STAGE_BYTES;
        const uint32_t Bsm = Asm + 16384;
        const int rsel = ((lane >> 4) << 3) + (lane & 7);
        const int csel = ((lane >> 3) & 1) << 3;
        #pragma unroll
        for (int kk = 0; kk < 4; kk++) {
            const int sRow = kk * 16 + rsel;
            uint32_t af[2][4];
            #pragma unroll
            for (int mi = 0; mi < 2; mi++) {
                int dcol = wm * 32 + mi * 16 + csel;
                int ch = (dcol >> 3) ^ (sRow & 7);
                LDSM4T(af[mi], Asm + sRow * 256 + ch * 16);
            }
            uint32_t bfr[4][4];
            #pragma unroll
            for (int nj = 0; nj < 4; nj++) {
                int ecol = wn * 64 + nj * 16 + csel;
                int ch = (ecol >> 3) ^ (sRow & 7);
                LDSM4T(bfr[nj], Bsm + sRow * 256 + ch * 16);
            }
            #pragma unroll
            for (int mi = 0; mi < 2; mi++)
                #pragma unroll
                for (int nj = 0; nj < 4; nj++) {
                    MMA16816(acc[mi][2*nj],   af[mi], bfr[nj][0], bfr[nj][2]);
                    MMA16816(acc[mi][2*nj+1], af[mi], bfr[nj][1], bfr[nj][3]);
                }
        }
    }

    float* outp = g_WsmP[split][z];
    #pragma unroll
    for (int mi = 0; mi < 2; mi++) {
        #pragma unroll
        for (int n8 = 0; n8 < 8; n8++) {
            const int e = wn * 64 + n8 * 8 + (lane & 3) * 2;
            #pragma unroll
            for (int hh = 0; hh < 2; hh++) {
                const int d = wm * 32 + mi * 16 + (lane >> 2) + hh * 8;
                *(float2*)(outp + d * DH_ + e) =
                    make_float2(acc[mi][n8][2*hh], acc[mi][n8][2*hh+1]);
            }
        }
    }
}

// ================= wvT via mma (single-sync) ============================
__global__ __launch_bounds__(256, 2) void wvt_mma(const __half* __restrict__ QKV)
{
    extern __shared__ char smem[];
    const uint32_t tiles = smem_u32(smem);
    const int tid = threadIdx.x;
    const int wid = tid >> 5, lane = tid & 31;
    const int wm = wid >> 1, wn = wid & 1;

    const int z = blockIdx.y, ntile = blockIdx.x;
    const int b = z >> 4, h = z & 15;
    const __half* Aw = g_w16 + (long long)z * (DH_ * DH_);
    const __half* Bv = QKV + ((long long)(b * S_ + ntile * 128)) * D3_ + 2 * D_ + h * DH_;

    float acc[2][8][4];
    #pragma unroll
    for (int i = 0; i < 2; i++)
        #pragma unroll
        for (int j = 0; j < 8; j++)
            #pragma unroll
            for (int q = 0; q < 4; q++) acc[i][j][q] = 0.0f;

    auto load_w = [&](uint32_t tA, uint32_t tB, long long k0) {
        #pragma unroll
        for (int i = 0; i < 4; i++) {
            int q = tid + 256 * i; int r = q >> 3, c = q & 7;
            cp16(tA + swz128(r * 128 + c * 16), Aw + (long long)r * DH_ + k0 + c * 8);
        }
        #pragma unroll
        for (int i = 0; i < 4; i++) {
            int q = tid + 256 * i; int r = q >> 3, c = q & 7;
            cp16(tB + swz128(r * 128 + c * 16), Bv + (long long)r * D3_ + k0 + c * 8);
        }
    };

    for (int s = 0; s < 2; s++) {
        load_w(tiles + s * STAGE_BYTES, tiles + s * STAGE_BYTES + 16384, (long long)s << 6);
        CP_COMMIT();
    }
    for (int m = 0; m < 2; m++) {
        cp_wait<1>();
        __syncthreads();
        CP_COMMIT();
        const uint32_t Asm = tiles + m * STAGE_BYTES;
        const uint32_t Bsm = Asm + 16384;
        #pragma unroll
        for (int kk = 0; kk < 4; kk++) {
            uint32_t af[2][4];
            #pragma unroll
            for (int mi = 0; mi < 2; mi++) {
                uint32_t addr = Asm + swz128((wm * 32 + mi * 16 + (lane & 15)) * 128
                                             + kk * 32 + (lane >> 4) * 16);
                LDSM4(af[mi], addr);
            }
            uint32_t bfr[4][4];
            #pragma unroll
            for (int nj = 0; nj < 4; nj++) {
                uint32_t addr = Bsm + swz128((wn * 64 + nj * 16 + (lane & 15)) * 128
                                             + kk * 32 + (lane >> 4) * 16);
                LDSM4(bfr[nj], addr);
            }
            #pragma unroll
            for (int mi = 0; mi < 2; mi++)
                #pragma unroll
                for (int nj = 0; nj < 4; nj++) {
                    MMA16816(acc[mi][2*nj],   af[mi], bfr[nj][0], bfr[nj][2]);
                    MMA16816(acc[mi][2*nj+1], af[mi], bfr[nj][1], bfr[nj][3]);
                }
        }
    }

    const long long tB = (long long)b * S_ + h * DH_;
    #pragma unroll
    for (int mi = 0; mi < 2; mi++) {
        #pragma unroll
        for (int n8 = 0; n8 < 8; n8++) {
            const int sL = wn * 64 + n8 * 8 + (lane & 3) * 2;
            const long long f = ntile * 128 + sL;
            #pragma unroll
            for (int hh = 0; hh < 2; hh++) {
                const int d = wm * 32 + mi * 16 + (lane >> 2) + hh * 8;
                *(__half2*)(g_A16 + (tB + d) * D_ + f) =
                    __halves2half2(__float2half(acc[mi][n8][2*hh]),
                                   __float2half(acc[mi][n8][2*hh+1]));
            }
        }
    }
}

// ================= fp32 -> fp16 conversion =================
__global__ void convert_h(const float* __restrict__ src, __half* __restrict__ dst, long long n)
{
    for (long long i = ((long long)blockIdx.x * blockDim.x + threadIdx.x) * 4; i < n;
         i += (long long)gridDim.x * blockDim.x * 4) {
        float4 v = *(const float4*)(src + i);
        *(__half2*)(dst + i)     = __halves2half2(__float2half(v.x), __float2half(v.y));
        *(__half2*)(dst + i + 2) = __halves2half2(__float2half(v.z), __float2half(v.w));
    }
}

// ================= softmax over e (128), fp16 out ========================
__global__ void softmax_kernel()
{
    int row = blockIdx.x;
    int z = row >> 7, d = row & 127;
    int e = threadIdx.x;
    float v = 0.0f;
    #pragma unroll
    for (int p = 0; p < GSPL; p++) v += g_WsmP[p][z][d * DH_ + e];
    v *= 0.022097086912079608f;
    __shared__ float red[128];
    red[e] = v; __syncthreads();
    for (int off = 64; off; off >>= 1) { if (e < off) red[e] = fmaxf(red[e], red[e+off]); __syncthreads(); }
    float mx = red[0];
    __syncthreads();
    float ex = __expf(v - mx);
    red[e] = ex; __syncthreads();
    for (int off = 64; off; off >>= 1) { if (e < off) red[e] += red[e+off]; __syncthreads(); }
    g_w16[z * (DH_ * DH_) + d * DH_ + e] = __float2half(ex / red[0]);
}

__global__ void reduce2_kernel(double n, int nparts)
{
    int t = threadIdx.x;
    double s = 0.0, ss = 0.0;
    for (int i = t; i < nparts; i += 256) { s += g_part[2*i]; ss += g_part[2*i+1]; }
    __shared__ double shs[256], shq[256];
    shs[t] = s; shq[t] = ss; __syncthreads();
    for (int off = 128; off; off >>= 1) {
        if (t < off) { shs[t] += shs[t+off]; shq[t] += shq[t+off]; }
        __syncthreads();
    }
    if (t == 0) {
        double mean = shs[0] / n;
        double var  = (shq[0] - n * mean * mean) / (n - 1.0);
        g_stats[0] = (float)mean;
        g_stats[1] = (float)(1.0 / sqrt(var + 1e-12));
    }
}

// LN apply: fp16 in -> fp16 out, 8-wide vectorized
__global__ void ln_apply_h16(const __half* __restrict__ xh, const float* __restrict__ w,
                             const float* __restrict__ bb, __half* __restrict__ y16, long long n)
{
    float mean = g_stats[0], inv = g_stats[1];
    for (long long i = ((long long)blockIdx.x * blockDim.x + threadIdx.x) * 8; i < n;
         i += (long long)gridDim.x * blockDim.x * 8) {
        int col = (int)(i & (D_ - 1));
        #pragma unroll
        for (int j = 0; j < 8; j += 2) {
            __half2 hv = *(const __half2*)(xh + i + j);
            float v0 = (__half2float(__low2half(hv))  - mean) * inv * w[col + j]     + bb[col + j];
            float v1 = (__half2float(__high2half(hv)) - mean) * inv * w[col + j + 1] + bb[col + j + 1];
            *(__half2*)(y16 + i + j) = __halves2half2(__float2half(v0), __float2half(v1));
        }
    }
}

// LN apply -> fp32 (final output)
__global__ void ln_apply_f_kernel(const float* __restrict__ x, const float* __restrict__ w,
                                  const float* __restrict__ bb, float* __restrict__ y, long long n)
{
    float mean = g_stats[0], inv = g_stats[1];
    for (long long i = (long long)blockIdx.x * blockDim.x + threadIdx.x; i < n;
         i += (long long)gridDim.x * blockDim.x) {
        int col = (int)(i & (D_ - 1));
        y[i] = (x[i] - mean) * inv * w[col] + bb[col];
    }
}

// ================= launcher =================
extern "C" void kernel_launch(void* const* d_in, const int* in_sizes, int n_in,
                              void* d_out, int out_size)
{
    const float* x      = (const float*)d_in[0];
    const float* W1_w   = (const float*)d_in[1];
    const float* W1_b   = (const float*)d_in[2];
    const float* W2_w   = (const float*)d_in[3];
    const float* W2_b   = (const float*)d_in[4];
    const float* fc_w   = (const float*)d_in[5];
    const float* fc_b   = (const float*)d_in[6];
    const float* proj_w = (const float*)d_in[7];
    const float* proj_b = (const float*)d_in[8];
    const float* ln1_w  = (const float*)d_in[9];
    const float* ln1_b  = (const float*)d_in[10];
    const float* ln2_w  = (const float*)d_in[11];
    const float* ln2_b  = (const float*)d_in[12];
    float* out = (float*)d_out;

    float *pR2;
    __half *px16, *pW116, *pW216, *pfc16, *ppj16, *pA16, *pL116, *pH16, *pQKV16, *pR1h;
    cudaGetSymbolAddress((void**)&pR2,    g_R2);
    cudaGetSymbolAddress((void**)&pR1h,   g_R1h);
    cudaGetSymbolAddress((void**)&px16,   g_x16);
    cudaGetSymbolAddress((void**)&pW116,  g_W116);
    cudaGetSymbolAddress((void**)&pW216,  g_W216);
    cudaGetSymbolAddress((void**)&pfc16,  g_fc16);
    cudaGetSymbolAddress((void**)&ppj16,  g_pj16);
    cudaGetSymbolAddress((void**)&pA16,   g_A16);
    cudaGetSymbolAddress((void**)&pL116,  g_L116);
    cudaGetSymbolAddress((void**)&pH16,   g_H16);
    cudaGetSymbolAddress((void**)&pQKV16, g_QKV16);

    cudaFuncSetAttribute(mma_gemm<false,false,false,true ,false>, cudaFuncAttributeMaxDynamicSharedMemorySize, TCG_SMEM);
    cudaFuncSetAttribute(mma_gemm<false,true ,false,true ,true >, cudaFuncAttributeMaxDynamicSharedMemorySize, TCG_SMEM);
    cudaFuncSetAttribute(mma_gemm<true ,false,false,true ,false>, cudaFuncAttributeMaxDynamicSharedMemorySize, TCG_SMEM);
    cudaFuncSetAttribute(mma_gemm<false,false,true ,false,true >, cudaFuncAttributeMaxDynamicSharedMemorySize, TCG_SMEM);
    cudaFuncSetAttribute(gram_mma, cudaFuncAttributeMaxDynamicSharedMemorySize, TCG_SMEM);
    cudaFuncSetAttribute(wvt_mma,  cudaFuncAttributeMaxDynamicSharedMemorySize, TCG_SMEM);

    static cudaStream_t s2 = nullptr, s3 = nullptr;
    static cudaEvent_t evFork = nullptr, evW1qk = nullptr, evW1v = nullptr, evX = nullptr,
                       evV = nullptr, evJoin = nullptr;
    if (s2 == nullptr) {
        cudaStreamCreate(&s2);
        cudaStreamCreate(&s3);
        cudaEventCreateWithFlags(&evFork, cudaEventDisableTiming);
        cudaEventCreateWithFlags(&evW1qk, cudaEventDisableTiming);
        cudaEventCreateWithFlags(&evW1v,  cudaEventDisableTiming);
        cudaEventCreateWithFlags(&evX,    cudaEventDisableTiming);
        cudaEventCreateWithFlags(&evV,    cudaEventDisableTiming);
        cudaEventCreateWithFlags(&evJoin, cudaEventDisableTiming);
    }

    const long long nLN = (long long)MTOK * D_;

    cudaEventRecord(evFork, 0);
    cudaStreamWaitEvent(s2, evFork, 0);
    cudaStreamWaitEvent(s3, evFork, 0);

    // s2: W1 convert split — QK rows first, then V rows, then late weights
    convert_h<<<2048, 256, 0, s2>>>(W1_w, pW116, (long long)4096 * D_);
    cudaEventRecord(evW1qk, s2);
    convert_h<<<1024, 256, 0, s2>>>(W1_w + (size_t)4096 * D_, pW116 + (size_t)4096 * D_,
                                    (long long)2048 * D_);
    cudaEventRecord(evW1v, s2);
    convert_h<<<1024, 256, 0, s2>>>(W2_w,   pW216, (long long)D_   * D_);
    convert_h<<<2048, 256, 0, s2>>>(fc_w,   pfc16, (long long)DFF_ * D_);
    convert_h<<<2048, 256, 0, s2>>>(proj_w, ppj16, (long long)D_ * DFF_);
    cudaEventRecord(evJoin, s2);

    // main: x convert
    convert_h<<<2048, 256>>>(x, px16, (long long)MTOK * D_);
    cudaEventRecord(evX, 0);

    // s3: V slice of QKV (cols 4096..6143) -> QKV16
    cudaStreamWaitEvent(s3, evW1v, 0);
    cudaStreamWaitEvent(s3, evX, 0);
    mma_gemm<false,false,false,true,false><<<dim3(16, MTOK/128), 256, TCG_SMEM, s3>>>(
        px16, pW116 + (size_t)4096 * D_, D_, W1_b + 4096, nullptr, nullptr,
        nullptr, pQKV16 + 4096, D3_);
    cudaEventRecord(evV, s3);

    // main: Q,K slice of QKV (cols 0..4095) -> QKV16
    cudaStreamWaitEvent(0, evW1qk, 0);
    mma_gemm<false,false,false,true,false><<<dim3(32, MTOK/128), 256, TCG_SMEM>>>(
        px16, pW116, D_, W1_b, nullptr, nullptr, nullptr, pQKV16, D3_);

    // gram (tensor core, split-4) + softmax -> fp16 probs
    gram_mma<<<dim3(64, GSPL), 256, TCG_SMEM>>>(pQKV16);
    softmax_kernel<<<64 * DH_, 128>>>();

    // join V, then wvT (tensor core)
    cudaStreamWaitEvent(0, evV, 0);
    wvt_mma<<<dim3(16, 64), 256, TCG_SMEM>>>(pQKV16);

    cudaStreamWaitEvent(0, evJoin, 0);

    // R1 = A @ W2^T + b + x  (fp32 resid from input; fp16 output; stats)
    mma_gemm<false,true,false,true,true><<<dim3(D_/128, MTOK/128), 256, TCG_SMEM>>>(
        pA16, pW216, D_, W2_b, x, nullptr, nullptr, pR1h, D_);

    // LN1: stats -> apply fp16->fp16
    reduce2_kernel<<<1, 256>>>((double)nLN, (D_/128) * (MTOK/128));
    ln_apply_h16<<<4096, 256>>>(pR1h, ln1_w, ln1_b, pL116, nLN);

    // H16 = fp16(gelu(LN1 @ fc^T + b))
    mma_gemm<true,false,false,true,false><<<dim3(DFF_/128, MTOK/128), 256, TCG_SMEM>>>(
        pL116, pfc16, D_, fc_b, nullptr, nullptr, nullptr, pH16, DFF_);

    // R2 = H @ proj^T + b + LN1(fp16 resid); fp32 out for final LN; stats
    mma_gemm<false,false,true,false,true><<<dim3(D_/128, MTOK/128), 256, TCG_SMEM>>>(
        pH16, ppj16, DFF_, proj_b, nullptr, pL116, pR2, nullptr, D_);

    // LN2 -> out
    reduce2_kernel<<<1, 256>>>((double)nLN, (D_/128) * (MTOK/128));
    ln_apply_f_kernel<<<8192, 256>>>(pR2, ln2_w, ln2_b, out, nLN);
}